// round 3
// baseline (speedup 1.0000x reference)
#include <cuda_runtime.h>

// Problem constants (fixed by the dataset)
#define MAXN 100352
#define MAXE 5000192
#define SCAN_TILE 4096            // 1024 threads * 4 elements
#define PERS_BLOCKS 296           // 2 per SM on 148 SMs (resident-guaranteed)
#define PERS_THREADS 512

// ---- scratch (static device globals; no allocation allowed) ----
__device__ int   g_count[MAXN];
__device__ int   g_rowptr[MAXN + 1];
__device__ int   g_cursor[MAXN];
__device__ int   g_col[MAXE];
__device__ float g_dinv[MAXN];
__device__ float g_z0[MAXN];
__device__ float g_zA[MAXN], g_zB[MAXN];
__device__ float g_yA[MAXN], g_yB[MAXN];
__device__ int   g_is64;
__device__ int   g_tilesum[64];
__device__ unsigned int g_bar;

// ---------------------------------------------------------------
// 0) zero counters + barrier + detect edge dtype (int64 LE -> odd words zero)
__global__ void zero_detect_kernel(const unsigned int* e, int N) {
    int i = blockIdx.x * blockDim.x + threadIdx.x;
    if (i < N) g_count[i] = 0;
    if (blockIdx.x == 0 && threadIdx.x == 0) {
        g_bar = 0u;
        int is64 = 1;
        #pragma unroll 1
        for (int k = 1; k < 1024; k += 2) {
            if (e[k] != 0u) { is64 = 0; break; }
        }
        g_is64 = is64;
    }
}

__device__ __forceinline__ int load_idx(const void* eidx, long long pos) {
    if (g_is64) return (int)((const long long*)eidx)[pos];
    return ((const int*)eidx)[pos];
}

// 1) in-degree histogram over dst
__global__ void hist_kernel(const void* eidx, int E) {
    int e = blockIdx.x * blockDim.x + threadIdx.x;
    if (e >= E) return;
    int d = load_idx(eidx, (long long)E + e);
    atomicAdd(&g_count[d], 1);
}

// ---------------- multi-block exclusive scan of g_count ----------------
// Pass A: per-tile totals
__global__ void scanA_kernel(int N) {
    __shared__ int wsum[32];
    int t = threadIdx.x;
    int base = blockIdx.x * SCAN_TILE + t * 4;
    int s = 0;
    #pragma unroll
    for (int j = 0; j < 4; j++) {
        int i = base + j;
        if (i < N) s += g_count[i];
    }
    #pragma unroll
    for (int o = 16; o; o >>= 1) s += __shfl_xor_sync(0xffffffffu, s, o);
    if ((t & 31) == 0) wsum[t >> 5] = s;
    __syncthreads();
    if (t < 32) {
        int v = wsum[t];
        #pragma unroll
        for (int o = 16; o; o >>= 1) v += __shfl_xor_sync(0xffffffffu, v, o);
        if (t == 0) g_tilesum[blockIdx.x] = v;
    }
}

// Pass C: per-tile exclusive scan -> rowptr (+cursor init, +dinv, +rowptr[N]).
// Each block computes its own tile prefix from g_tilesum (no scanB).
__global__ void scanC_kernel(int N, int ntiles) {
    __shared__ int wsum[32];
    __shared__ int s_tileoff;
    int t = threadIdx.x;
    int lane = t & 31;
    int warp = t >> 5;

    if (t < 32) {
        int s = 0;
        #pragma unroll
        for (int j = 0; j < 2; j++) {
            int idx = t + j * 32;
            int v = (idx < ntiles && idx < blockIdx.x) ? g_tilesum[idx] : 0;
            s += v;
        }
        #pragma unroll
        for (int o = 16; o; o >>= 1) s += __shfl_xor_sync(0xffffffffu, s, o);
        if (t == 0) s_tileoff = s;
    }

    int base = blockIdx.x * SCAN_TILE + t * 4;
    int c[4];
    #pragma unroll
    for (int j = 0; j < 4; j++) {
        int i = base + j;
        c[j] = (i < N) ? g_count[i] : 0;
    }
    int local = c[0] + c[1] + c[2] + c[3];

    // inclusive scan of `local` within warp
    int inc = local;
    #pragma unroll
    for (int o = 1; o < 32; o <<= 1) {
        int v = __shfl_up_sync(0xffffffffu, inc, o);
        if (lane >= o) inc += v;
    }
    if (lane == 31) wsum[warp] = inc;
    __syncthreads();
    if (t < 32) {
        int v = wsum[t];
        int iv = v;
        #pragma unroll
        for (int o = 1; o < 32; o <<= 1) {
            int u = __shfl_up_sync(0xffffffffu, iv, o);
            if (lane >= o) iv += u;
        }
        wsum[t] = iv - v;   // exclusive warp offsets
    }
    __syncthreads();
    int off = s_tileoff + wsum[warp] + (inc - local);
    #pragma unroll
    for (int j = 0; j < 4; j++) {
        int i = base + j;
        if (i < N) {
            g_rowptr[i] = off;
            g_cursor[i] = off;
            g_dinv[i] = rsqrtf((float)c[j] + 1.0f);
            if (i == N - 1) g_rowptr[N] = off + c[j];
            off += c[j];
        }
    }
}

// 2) CSR placement: cursor pre-initialized to rowptr
__global__ void place_kernel(const void* eidx, int E) {
    int e = blockIdx.x * blockDim.x + threadIdx.x;
    if (e >= E) return;
    int s = load_idx(eidx, e);
    int d = load_idx(eidx, (long long)E + e);
    int idx = atomicAdd(&g_cursor[d], 1);
    g_col[idx] = s;
}

// ---------------- persistent fused kernel ----------------
// grid barrier: release-arrive + acquire-spin on monotonic counter
__device__ __forceinline__ void grid_barrier(unsigned int target) {
    __syncthreads();
    if (threadIdx.x == 0) {
        unsigned int* bar = &g_bar;
        asm volatile("red.release.gpu.add.u32 [%0], 1;" :: "l"(bar) : "memory");
        unsigned int v;
        while (true) {
            asm volatile("ld.acquire.gpu.u32 %0, [%1];" : "=r"(v) : "l"(bar) : "memory");
            if (v >= target) break;
            __nanosleep(64);
        }
    }
    __syncthreads();
}

__global__ void __launch_bounds__(PERS_THREADS, 2)
appnp_kernel(const float* __restrict__ x,
             const float* __restrict__ W1, const float* __restrict__ b1,
             const float* __restrict__ W2, const float* __restrict__ b2,
             const float* __restrict__ W3, const float* __restrict__ b3,
             float* __restrict__ out, int N) {
    __shared__ float sW2[256], sW1[16], sb1[16], sb2[16], sW3[16];
    int t = threadIdx.x;
    if (t < 256) sW2[t] = W2[t];
    if (t < 16) { sW1[t] = W1[t]; sb1[t] = b1[t]; sb2[t] = b2[t]; sW3[t] = W3[t]; }
    __syncthreads();

    int gsize = gridDim.x * blockDim.x;
    int gtid = blockIdx.x * blockDim.x + t;

    // --- encoder collapsed to scalar: z0 = relu(relu(x*W1+b1)@W2+b2)@W3 ---
    for (int i = gtid; i < N; i += gsize) {
        float xv = __ldg(&x[i]);
        float h1[16];
        #pragma unroll
        for (int j = 0; j < 16; j++) h1[j] = fmaxf(xv * sW1[j] + sb1[j], 0.0f);
        float z = 0.0f;
        #pragma unroll
        for (int j = 0; j < 16; j++) {
            float a = sb2[j];
            #pragma unroll
            for (int k = 0; k < 16; k++) a = fmaf(h1[k], sW2[k * 16 + j], a);
            z = fmaf(fmaxf(a, 0.0f), sW3[j], z);
        }
        float di = g_dinv[i];
        g_z0[i] = z;
        g_zA[i] = z;
        g_yA[i] = di * z;
    }

    unsigned int bar_target = gridDim.x;
    grid_barrier(bar_target);

    int nwarps = gsize >> 5;
    int gw0 = gtid >> 5;
    int lane = t & 31;

    float* zin = g_zA; float* zout = g_zB;
    float* yin = g_yA; float* yout = g_yB;

    // --- K = 10 propagation iterations ---
    #pragma unroll 1
    for (int k = 0; k < 10; k++) {
        #pragma unroll 1
        for (int row = gw0; row < N; row += nwarps) {
            int beg = __ldg(&g_rowptr[row]);
            int end = __ldg(&g_rowptr[row + 1]);
            float s = 0.0f;
            #pragma unroll 1
            for (int e = beg + lane; e < end; e += 32)
                s += __ldcg(&yin[__ldg(&g_col[e])]);
            #pragma unroll
            for (int o = 16; o; o >>= 1) s += __shfl_xor_sync(0xffffffffu, s, o);
            if (lane == 0) {
                float di = g_dinv[row];
                float agg = fmaf(di, s, di * di * __ldcg(&zin[row]));
                float zn = fmaf(0.9f, agg, 0.1f * __ldg(&g_z0[row]));
                __stcg(&zout[row], zn);
                __stcg(&yout[row], di * zn);
            }
        }
        bar_target += gridDim.x;
        grid_barrier(bar_target);
        float* tp;
        tp = zin; zin = zout; zout = tp;
        tp = yin; yin = yout; yout = tp;
    }

    // --- final: out = z + b3 (after 10 swaps z lives in zin = g_zA) ---
    float bb = __ldg(&b3[0]);
    for (int i = gtid; i < N; i += gsize)
        out[i] = __ldcg(&zin[i]) + bb;
}

extern "C" void kernel_launch(void* const* d_in, const int* in_sizes, int n_in,
                              void* d_out, int out_size) {
    const float* x  = (const float*)d_in[0];
    const void*  ei = d_in[1];
    const float* W1 = (const float*)d_in[2];
    const float* b1 = (const float*)d_in[3];
    const float* W2 = (const float*)d_in[4];
    const float* b2 = (const float*)d_in[5];
    const float* W3 = (const float*)d_in[6];
    const float* b3 = (const float*)d_in[7];
    float* out = (float*)d_out;

    int N = in_sizes[0];          // x is [N,1]
    int E = in_sizes[1] / 2;      // edge_index is [2,E]

    int nb = (N + 255) / 256;
    int eb = (E + 255) / 256;
    int ntiles = (N + SCAN_TILE - 1) / SCAN_TILE;

    zero_detect_kernel<<<nb, 256>>>((const unsigned int*)ei, N);
    hist_kernel<<<eb, 256>>>(ei, E);
    scanA_kernel<<<ntiles, 1024>>>(N);
    scanC_kernel<<<ntiles, 1024>>>(N, ntiles);
    place_kernel<<<eb, 256>>>(ei, E);
    appnp_kernel<<<PERS_BLOCKS, PERS_THREADS>>>(x, W1, b1, W2, b2, W3, b3, out, N);
}